// round 7
// baseline (speedup 1.0000x reference)
#include <cuda_runtime.h>
#include <math.h>
#include <cstdint>

// Problem constants: B=4, L=2048, D=1024, H=16, Dh=64, 3D=3072
#define BATCH   4
#define SEQ     2048
#define EMBD    1024
#define NHEAD   16
#define HDIM    64
#define TOKENS  (BATCH * SEQ)            // 8192
#define QKVDIM  (3 * EMBD)               // 3072

// ---------------- scratch (static __device__, no allocation) ----------------
__device__ float g_q[(size_t)BATCH * NHEAD * SEQ * HDIM]; // [B,H,L,Dh] tf32, /8
__device__ float g_k[(size_t)BATCH * NHEAD * SEQ * HDIM]; // tf32
__device__ float g_v[(size_t)BATCH * NHEAD * SEQ * HDIM]; // tf32
__device__ float g_att[(size_t)TOKENS * EMBD];            // [B,L,D] tf32, k-perm
__device__ float2 g_rope[(size_t)SEQ * 32];               // cos/sin table
__device__ float g_xc[(size_t)TOKENS * EMBD];             // x tf32, k-perm
__device__ float g_wqkvT[(size_t)QKVDIM * EMBD];          // W_qkv^T tf32, k-perm
__device__ float g_wprojT[(size_t)EMBD * EMBD];           // W_proj^T tf32, k-perm

// ---------------- helpers ----------------------------------------------
__device__ __forceinline__ uint32_t f2tf32(float x) {
  uint32_t u;
  asm("cvt.rna.tf32.f32 %0, %1;" : "=r"(u) : "f"(x));
  return u;
}
__device__ __forceinline__ float f2tf32f(float x) {
  return __uint_as_float(f2tf32(x));
}

__device__ __forceinline__ void mma_tf32(float* d, const uint32_t* a,
                                         const uint32_t* b) {
  asm volatile(
      "mma.sync.aligned.m16n8k8.row.col.f32.tf32.tf32.f32 "
      "{%0,%1,%2,%3},{%4,%5,%6,%7},{%8,%9},{%0,%1,%2,%3};"
      : "+f"(d[0]), "+f"(d[1]), "+f"(d[2]), "+f"(d[3])
      : "r"(a[0]), "r"(a[1]), "r"(a[2]), "r"(a[3]), "r"(b[0]), "r"(b[1]));
}

#define CPA16(dst, src) \
  asm volatile("cp.async.cg.shared.global [%0], [%1], 16;\n" ::"r"(dst), "l"(src))

// k-permutation within each 8-group: old k -> new position
__device__ __host__ __forceinline__ int kperm(int k) {
  return (k & ~7) | ((k & 3) * 2 + ((k & 7) >> 2));
}

// ---------------- RoPE cos/sin table ----------------------------------------
__global__ __launch_bounds__(256) void rope_table_kernel() {
  const int idx = blockIdx.x * 256 + threadIdx.x;  // 0..65535
  const int l = idx >> 5, i = idx & 31;
  const float inv_freq = 1.0f / powf(10000.0f, (2.0f * (float)i) / 64.0f);
  float s, c;
  sincosf((float)l * inv_freq, &s, &c);
  g_rope[idx] = make_float2(c, s);
}

// ------------- round to tf32 + permute k within rows (for A operands) -------
__global__ __launch_bounds__(256) void round_permute_kernel(
    const float* __restrict__ in, float* __restrict__ out, int n8) {
  int i = blockIdx.x * 256 + threadIdx.x;  // one 8-float group per thread
  const int stride = gridDim.x * 256;
  for (; i < n8; i += stride) {
    const float4 a = ((const float4*)in)[2 * i];
    const float4 b = ((const float4*)in)[2 * i + 1];
    float2* o = (float2*)(out + 8 * (size_t)i);
    o[0] = make_float2(f2tf32f(a.x), f2tf32f(b.x));
    o[1] = make_float2(f2tf32f(a.y), f2tf32f(b.y));
    o[2] = make_float2(f2tf32f(a.z), f2tf32f(b.z));
    o[3] = make_float2(f2tf32f(a.w), f2tf32f(b.w));
  }
}

// ------------- transpose + round + permute (for weight / B operands) --------
// in: [K][N] row-major -> out: [N][K] with k permuted, tf32 rounded
__global__ __launch_bounds__(256) void transpose_permute_kernel(
    const float* __restrict__ in, float* __restrict__ out, int K, int N) {
  __shared__ float tile[32][33];
  const int k0 = blockIdx.y * 32, n0 = blockIdx.x * 32;
  const int tx = threadIdx.x, ty = threadIdx.y;  // 32 x 8
#pragma unroll
  for (int i = 0; i < 32; i += 8)
    tile[ty + i][tx] = in[(size_t)(k0 + ty + i) * N + n0 + tx];
  __syncthreads();
  const int pk = kperm(tx);
#pragma unroll
  for (int i = 0; i < 32; i += 8) {
    const int n = ty + i;
    out[(size_t)(n0 + n) * K + k0 + pk] = f2tf32f(tile[tx][n]);
  }
}

// ---------------- GEMM core -------------------------------------------------
// A: [M][K] k-permuted; BT: [N][K] k-permuted. All fragment loads LDS.64.
#define AB_STRIDE 40
#define AB_BUF (128 * AB_STRIDE)  // 5120 floats
#define GEMM_SMEM (4 * AB_BUF * 4)  // 81920 B

__device__ __forceinline__ void gemm_tile_compute(
    const float* __restrict__ A, const float* __restrict__ BT, float* sm,
    int m0, int n0, int K, float acc[4][4][4]) {
  const int tid = threadIdx.x;
  const int warp = tid >> 5, lane = tid & 31;
  const int wm = warp >> 2, wn = warp & 3;
  const int g = lane >> 2, tig = lane & 3;

#pragma unroll
  for (int i = 0; i < 4; i++)
#pragma unroll
    for (int j = 0; j < 4; j++)
#pragma unroll
      for (int t = 0; t < 4; t++) acc[i][j][t] = 0.0f;

  auto prefetch = [&](int kt, int buf) {
    float* As = sm + buf * AB_BUF;
    float* Bs = sm + 2 * AB_BUF + buf * AB_BUF;
    const int k0 = kt << 5;
#pragma unroll
    for (int j = 0; j < 4; j++) {
      const int p = tid + (j << 8);
      const int r = p >> 3, c4 = (p & 7) << 2;  // 128 rows x 8 float4
      uint32_t da = (uint32_t)__cvta_generic_to_shared(As + r * AB_STRIDE + c4);
      CPA16(da, A + (size_t)(m0 + r) * K + k0 + c4);
      uint32_t db = (uint32_t)__cvta_generic_to_shared(Bs + r * AB_STRIDE + c4);
      CPA16(db, BT + (size_t)(n0 + r) * K + k0 + c4);
    }
    asm volatile("cp.async.commit_group;\n");
  };

  const int NT = K >> 5;
  prefetch(0, 0);

  for (int kt = 0; kt < NT; kt++) {
    const int buf = kt & 1;
    if (kt + 1 < NT) {
      prefetch(kt + 1, buf ^ 1);
      asm volatile("cp.async.wait_group 1;\n");
    } else {
      asm volatile("cp.async.wait_group 0;\n");
    }
    __syncthreads();

    const float* As = sm + buf * AB_BUF;
    const float* Bs = sm + 2 * AB_BUF + buf * AB_BUF;

#pragma unroll
    for (int ks = 0; ks < 4; ks++) {
      const int koff = ks * 8 + 2 * tig;
      uint32_t af[4][4], bf[4][2];
#pragma unroll
      for (int mt = 0; mt < 4; mt++) {
        const int row = wm * 64 + mt * 16 + g;
        float2 a02 = *(const float2*)(As + row * AB_STRIDE + koff);
        float2 a13 = *(const float2*)(As + (row + 8) * AB_STRIDE + koff);
        af[mt][0] = __float_as_uint(a02.x);
        af[mt][2] = __float_as_uint(a02.y);
        af[mt][1] = __float_as_uint(a13.x);
        af[mt][3] = __float_as_uint(a13.y);
      }
#pragma unroll
      for (int nt = 0; nt < 4; nt++) {
        const int nrow = wn * 32 + nt * 8 + g;
        float2 b01 = *(const float2*)(Bs + nrow * AB_STRIDE + koff);
        bf[nt][0] = __float_as_uint(b01.x);
        bf[nt][1] = __float_as_uint(b01.y);
      }
#pragma unroll
      for (int mt = 0; mt < 4; mt++)
#pragma unroll
        for (int nt = 0; nt < 4; nt++) mma_tf32(acc[mt][nt], af[mt], bf[nt]);
    }
    __syncthreads();
  }
}

// ---------------- plain GEMM + bias (used for proj) -------------------------
__global__ __launch_bounds__(256) void gemm_tf32_kernel(
    const float* __restrict__ A, const float* __restrict__ BT,
    const float* __restrict__ bias, float* __restrict__ C, int N, int K) {
  extern __shared__ float sm[];
  const int tid = threadIdx.x;
  const int warp = tid >> 5, lane = tid & 31;
  const int wm = warp >> 2, wn = warp & 3;
  const int g = lane >> 2, tig = lane & 3;
  const int m0 = blockIdx.y << 7, n0 = blockIdx.x << 7;

  float acc[4][4][4];
  gemm_tile_compute(A, BT, sm, m0, n0, K, acc);

#pragma unroll
  for (int mt = 0; mt < 4; mt++) {
    const int r = m0 + wm * 64 + mt * 16 + g;
#pragma unroll
    for (int nt = 0; nt < 4; nt++) {
      const int c = n0 + wn * 32 + nt * 8 + 2 * tig;
      const float b0 = __ldg(bias + c), b1 = __ldg(bias + c + 1);
      float2 v0 = {acc[mt][nt][0] + b0, acc[mt][nt][1] + b1};
      float2 v1 = {acc[mt][nt][2] + b0, acc[mt][nt][3] + b1};
      *(float2*)(C + (size_t)r * N + c) = v0;
      *(float2*)(C + (size_t)(r + 8) * N + c) = v1;
    }
  }
}

// ---------------- QKV GEMM with fused RoPE/split epilogue -------------------
__global__ __launch_bounds__(256) void gemm_qkv_rope_kernel(
    const float* __restrict__ A, const float* __restrict__ BT,
    const float* __restrict__ bias, float* __restrict__ Q,
    float* __restrict__ K, float* __restrict__ V) {
  extern __shared__ float sm[];
  const int tid = threadIdx.x;
  const int warp = tid >> 5, lane = tid & 31;
  const int wm = warp >> 2, wn = warp & 3;
  const int g = lane >> 2, tig = lane & 3;
  const int m0 = blockIdx.y << 7, n0 = blockIdx.x << 7;

  float acc[4][4][4];
  gemm_tile_compute(A, BT, sm, m0, n0, EMBD, acc);

  const int seg = n0 >> 10;  // 0=q, 1=k, 2=v (block-uniform)
  float* dst = (seg == 0) ? Q : (seg == 1) ? K : V;

#pragma unroll
  for (int mt = 0; mt < 4; mt++) {
    const int r = m0 + wm * 64 + mt * 16 + g;  // token row (and r+8)
#pragma unroll
    for (int nt = 0; nt < 4; nt++) {
      const int c = n0 + wn * 32 + nt * 8 + 2 * tig;  // even column
      const float b0 = __ldg(bias + c), b1 = __ldg(bias + c + 1);
      const int d = c & 63;            // dim within head (even)
      const int h = (c & 1023) >> 6;   // head
      const int i = d >> 1;            // rope pair index
      float vals[2][2] = {{acc[mt][nt][0] + b0, acc[mt][nt][1] + b1},
                          {acc[mt][nt][2] + b0, acc[mt][nt][3] + b1}};
#pragma unroll
      for (int rr = 0; rr < 2; rr++) {
        const int m = r + rr * 8;
        const int bb = m >> 11, l = m & 2047;
        float* o = dst + ((size_t)(bb * NHEAD + h) * SEQ + l) * HDIM + d;
        const float x1 = vals[rr][0], x2 = vals[rr][1];
        float2 w;
        if (seg == 0) {
          const float2 cs = g_rope[l * 32 + i];
          w.x = f2tf32f((x1 * cs.x - x2 * cs.y) * 0.125f);
          w.y = f2tf32f((x1 * cs.y + x2 * cs.x) * 0.125f);
        } else if (seg == 1) {
          const float2 cs = g_rope[l * 32 + i];
          w.x = f2tf32f(x1 * cs.x - x2 * cs.y);
          w.y = f2tf32f(x1 * cs.y + x2 * cs.x);
        } else {
          w.x = f2tf32f(x1);
          w.y = f2tf32f(x2);
        }
        *(float2*)o = w;
      }
    }
  }
}

// ---------------- tensor-core causal flash attention ------------------------
// 128 q-rows per block, 8 warps (16 rows each), BN=64 keys/tile,
// K/V double-buffered cp.async. Q fragments in registers.
// Epilogue writes att in k-permuted layout for the proj GEMM.
#define KS_STRIDE 68
#define VS_STRIDE 72
#define PS_STRIDE 68
#define KBUF (64 * KS_STRIDE)
#define VBUF (64 * VS_STRIDE)
#define FLASH_SMEM ((2 * (KBUF + VBUF) + 128 * PS_STRIDE) * 4 + 2 * 64 * 4)

__global__ __launch_bounds__(256, 2) void flash_mma_kernel(
    const float* __restrict__ Q, const float* __restrict__ K,
    const float* __restrict__ V, const int* __restrict__ amask,
    float* __restrict__ O) {
  extern __shared__ float smf[];
  float* Ksb = smf;                    // 2 buffers
  float* Vsb = Ksb + 2 * KBUF;         // 2 buffers
  float* Ps = Vsb + 2 * VBUF;          // 128 rows
  int* msk = (int*)(Ps + 128 * PS_STRIDE);  // [2][64]

  const int tid = threadIdx.x;
  const int warp = tid >> 5, lane = tid & 31;
  const int g = lane >> 2, tig = lane & 3;
  const int bx = (int)(gridDim.x - 1 - blockIdx.x);  // heavy blocks first
  const int h = blockIdx.y, b = blockIdx.z;
  const int q0 = bx << 7;
  const size_t base = (size_t)(b * NHEAD + h) * SEQ * HDIM;

  // ---- stage Q tile (128x64) through Ps, hoist fragments to registers ----
#pragma unroll
  for (int i = 0; i < 8; i++) {
    const int p = tid + (i << 8);
    const int r = p >> 4, c = (p & 15) << 2;
    *(float4*)(Ps + r * PS_STRIDE + c) =
        *(const float4*)(Q + base + (size_t)(q0 + r) * HDIM + c);
  }
  __syncthreads();
  uint32_t qf[8][4];
  {
    const float* qb = Ps + (warp * 16 + g) * PS_STRIDE;
#pragma unroll
    for (int kc = 0; kc < 8; kc++) {
      const int kk = kc << 3;
      qf[kc][0] = __float_as_uint(qb[kk + tig]);
      qf[kc][1] = __float_as_uint(qb[8 * PS_STRIDE + kk + tig]);
      qf[kc][2] = __float_as_uint(qb[kk + tig + 4]);
      qf[kc][3] = __float_as_uint(qb[8 * PS_STRIDE + kk + tig + 4]);
    }
  }
  __syncthreads();  // Ps becomes per-warp P staging

  auto prefetch = [&](int kt, int buf) {
    const int k0 = kt << 6;
    float* Ks = Ksb + buf * KBUF;
    float* Vs = Vsb + buf * VBUF;
#pragma unroll
    for (int i = 0; i < 4; i++) {
      const int p = tid + (i << 8);
      const int r = p >> 4, c = (p & 15) << 2;
      uint32_t dk = (uint32_t)__cvta_generic_to_shared(Ks + r * KS_STRIDE + c);
      CPA16(dk, K + base + (size_t)(k0 + r) * HDIM + c);
      uint32_t dv = (uint32_t)__cvta_generic_to_shared(Vs + r * VS_STRIDE + c);
      CPA16(dv, V + base + (size_t)(k0 + r) * HDIM + c);
    }
    if (tid < 64) msk[buf * 64 + tid] = amask[b * SEQ + k0 + tid];
  };

  float m0 = -1e30f, m1 = -1e30f, l0 = 0.0f, l1 = 0.0f;
  float o[8][4];
#pragma unroll
  for (int nt = 0; nt < 8; nt++)
#pragma unroll
    for (int c = 0; c < 4; c++) o[nt][c] = 0.0f;

  const int NT = (q0 >> 6) + 2;  // tiles 0..NT-1; last two are boundary tiles
  const int rg0 = q0 + warp * 16 + g;  // global row for acc slots 0/1 (+8: 2/3)

  prefetch(0, 0);
  asm volatile("cp.async.commit_group;\n");

  for (int kt = 0; kt < NT; kt++) {
    const int buf = kt & 1;
    if (kt + 1 < NT) prefetch(kt + 1, buf ^ 1);
    asm volatile("cp.async.commit_group;\n");
    asm volatile("cp.async.wait_group 1;\n");
    __syncthreads();

    const float* Ks = Ksb + buf * KBUF;
    const float* Vs = Vsb + buf * VBUF;
    const int* mk = msk + buf * 64;

    // ---- S = (Q/8) @ K^T ----
    float s[8][4];
#pragma unroll
    for (int nt = 0; nt < 8; nt++)
#pragma unroll
      for (int c = 0; c < 4; c++) s[nt][c] = 0.0f;

#pragma unroll
    for (int kc = 0; kc < 8; kc++) {
      const int kk = kc << 3;
#pragma unroll
      for (int nt = 0; nt < 8; nt++) {
        const float* kb = Ks + (nt * 8 + g) * KS_STRIDE + kk;
        uint32_t bf[2];
        bf[0] = __float_as_uint(kb[tig]);
        bf[1] = __float_as_uint(kb[tig + 4]);
        mma_tf32(s[nt], qf[kc], bf);
      }
    }

    // ---- mask ----
    if (kt >= NT - 2) {
      const int k0 = kt << 6;
#pragma unroll
      for (int nt = 0; nt < 8; nt++) {
        const int cg = k0 + nt * 8 + 2 * tig;  // global col (and +1)
        const int m_a = mk[nt * 8 + 2 * tig], m_b = mk[nt * 8 + 2 * tig + 1];
        if (!(m_a && cg <= rg0)) s[nt][0] = -1e30f;
        if (!(m_b && cg + 1 <= rg0)) s[nt][1] = -1e30f;
        if (!(m_a && cg <= rg0 + 8)) s[nt][2] = -1e30f;
        if (!(m_b && cg + 1 <= rg0 + 8)) s[nt][3] = -1e30f;
      }
    } else {
#pragma unroll
      for (int nt = 0; nt < 8; nt++) {
        const int m_a = mk[nt * 8 + 2 * tig], m_b = mk[nt * 8 + 2 * tig + 1];
        if (!m_a) { s[nt][0] = -1e30f; s[nt][2] = -1e30f; }
        if (!m_b) { s[nt][1] = -1e30f; s[nt][3] = -1e30f; }
      }
    }

    // ---- online softmax ----
    float mx0 = -1e30f, mx1 = -1e30f;
#pragma unroll
    for (int nt = 0; nt < 8; nt++) {
      mx0 = fmaxf(mx0, fmaxf(s[nt][0], s[nt][1]));
      mx1 = fmaxf(mx1, fmaxf(s[nt][2], s[nt][3]));
    }
    mx0 = fmaxf(mx0, __shfl_xor_sync(0xffffffffu, mx0, 1));
    mx0 = fmaxf(mx0, __shfl_xor_sync(0xffffffffu, mx0, 2));
    mx1 = fmaxf(mx1, __shfl_xor_sync(0xffffffffu, mx1, 1));
    mx1 = fmaxf(mx1, __shfl_xor_sync(0xffffffffu, mx1, 2));
    const float nm0 = fmaxf(m0, mx0), nm1 = fmaxf(m1, mx1);
    const float corr0 = __expf(m0 - nm0), corr1 = __expf(m1 - nm1);
    m0 = nm0;
    m1 = nm1;

    float sum0 = 0.0f, sum1 = 0.0f;
#pragma unroll
    for (int nt = 0; nt < 8; nt++) {
      s[nt][0] = __expf(s[nt][0] - nm0);
      s[nt][1] = __expf(s[nt][1] - nm0);
      s[nt][2] = __expf(s[nt][2] - nm1);
      s[nt][3] = __expf(s[nt][3] - nm1);
      sum0 += s[nt][0] + s[nt][1];
      sum1 += s[nt][2] + s[nt][3];
    }
    sum0 += __shfl_xor_sync(0xffffffffu, sum0, 1);
    sum0 += __shfl_xor_sync(0xffffffffu, sum0, 2);
    sum1 += __shfl_xor_sync(0xffffffffu, sum1, 1);
    sum1 += __shfl_xor_sync(0xffffffffu, sum1, 2);
    l0 = l0 * corr0 + sum0;
    l1 = l1 * corr1 + sum1;

#pragma unroll
    for (int nt = 0; nt < 8; nt++) {
      o[nt][0] *= corr0;
      o[nt][1] *= corr0;
      o[nt][2] *= corr1;
      o[nt][3] *= corr1;
    }

    // ---- stage P (C-layout -> A-layout) in per-warp Ps region ----
    float* pr = Ps + (warp * 16 + g) * PS_STRIDE;
#pragma unroll
    for (int nt = 0; nt < 8; nt++) {
      const int c0 = nt * 8 + 2 * tig;
      pr[c0] = f2tf32f(s[nt][0]);
      pr[c0 + 1] = f2tf32f(s[nt][1]);
      pr[8 * PS_STRIDE + c0] = f2tf32f(s[nt][2]);
      pr[8 * PS_STRIDE + c0 + 1] = f2tf32f(s[nt][3]);
    }
    __syncwarp();

    // ---- O += P @ V ----
    const float* pb = Ps + (warp * 16 + g) * PS_STRIDE;
#pragma unroll
    for (int kc = 0; kc < 8; kc++) {
      const int kk = kc << 3;
      uint32_t a[4];
      a[0] = __float_as_uint(pb[kk + tig]);
      a[1] = __float_as_uint(pb[8 * PS_STRIDE + kk + tig]);
      a[2] = __float_as_uint(pb[kk + tig + 4]);
      a[3] = __float_as_uint(pb[8 * PS_STRIDE + kk + tig + 4]);
#pragma unroll
      for (int nt = 0; nt < 8; nt++) {
        const float* vb = Vs + (kk + tig) * VS_STRIDE + nt * 8 + g;
        uint32_t bf[2];
        bf[0] = __float_as_uint(vb[0]);
        bf[1] = __float_as_uint(vb[4 * VS_STRIDE]);
        mma_tf32(o[nt], a, bf);
      }
    }
    __syncthreads();  // all warps done with Ks/Vs[buf] before refill
  }

  // ---- write O / l to [B, L, H*Dh] k-PERMUTED layout (proj GEMM A side) ----
  const float inv0 = 1.0f / l0, inv1 = 1.0f / l1;
#pragma unroll
  for (int nt = 0; nt < 8; nt++) {
    const int cbase = h * HDIM + nt * 8;
    const int ca = cbase + kperm(2 * tig);      // permuted pos of col 2t
    const int cb = cbase + kperm(2 * tig + 1);  // permuted pos of col 2t+1
    float* r0p = O + (size_t)(b * SEQ + rg0) * EMBD;
    float* r1p = O + (size_t)(b * SEQ + rg0 + 8) * EMBD;
    r0p[ca] = f2tf32f(o[nt][0] * inv0);
    r0p[cb] = f2tf32f(o[nt][1] * inv0);
    r1p[ca] = f2tf32f(o[nt][2] * inv1);
    r1p[cb] = f2tf32f(o[nt][3] * inv1);
  }
}

// ---------------------------------------------------------------------------
extern "C" void kernel_launch(void* const* d_in, const int* in_sizes, int n_in,
                              void* d_out, int out_size) {
  const float* x     = (const float*)d_in[0];
  const float* Wqkv  = (const float*)d_in[1];
  const float* bqkv  = (const float*)d_in[2];
  const float* Wproj = (const float*)d_in[3];
  const float* bproj = (const float*)d_in[4];
  const int*   amask = (const int*)d_in[5];
  float* out = (float*)d_out;

  float *q, *k, *v, *att, *xc, *wqkvT, *wprojT;
  cudaGetSymbolAddress((void**)&q, g_q);
  cudaGetSymbolAddress((void**)&k, g_k);
  cudaGetSymbolAddress((void**)&v, g_v);
  cudaGetSymbolAddress((void**)&att, g_att);
  cudaGetSymbolAddress((void**)&xc, g_xc);
  cudaGetSymbolAddress((void**)&wqkvT, g_wqkvT);
  cudaGetSymbolAddress((void**)&wprojT, g_wprojT);

  cudaFuncSetAttribute(gemm_tf32_kernel,
                       cudaFuncAttributeMaxDynamicSharedMemorySize, GEMM_SMEM);
  cudaFuncSetAttribute(gemm_qkv_rope_kernel,
                       cudaFuncAttributeMaxDynamicSharedMemorySize, GEMM_SMEM);
  cudaFuncSetAttribute(flash_mma_kernel,
                       cudaFuncAttributeMaxDynamicSharedMemorySize, FLASH_SMEM);

  // 0. RoPE table + operand preparation (round/permute/transpose)
  rope_table_kernel<<<SEQ * 32 / 256, 256>>>();
  round_permute_kernel<<<1184, 256>>>(x, xc, TOKENS * EMBD / 8);
  {
    dim3 gt1(QKVDIM / 32, EMBD / 32);
    transpose_permute_kernel<<<gt1, dim3(32, 8)>>>(Wqkv, wqkvT, EMBD, QKVDIM);
    dim3 gt2(EMBD / 32, EMBD / 32);
    transpose_permute_kernel<<<gt2, dim3(32, 8)>>>(Wproj, wprojT, EMBD, EMBD);
  }

  // 1. QKV projection + fused RoPE/split -> g_q (/8), g_k, g_v in [B,H,L,Dh]
  dim3 g1(QKVDIM / 128, TOKENS / 128);
  gemm_qkv_rope_kernel<<<g1, 256, GEMM_SMEM>>>(xc, wqkvT, bqkv, q, k, v);

  // 2. Causal flash attention (tensor cores, BM=128) -> att (k-permuted)
  dim3 g3(SEQ / 128, NHEAD, BATCH);
  flash_mma_kernel<<<g3, 256, FLASH_SMEM>>>(q, k, v, amask, att);

  // 3. Output projection: [8192,1024] @ [1024,1024]^T(pre-transposed)
  dim3 g4(EMBD / 128, TOKENS / 128);
  gemm_tf32_kernel<<<g4, 256, GEMM_SMEM>>>(att, wprojT, bproj, out,
                                           EMBD, EMBD);
}

// round 8
// speedup vs baseline: 1.6740x; 1.6740x over previous
#include <cuda_runtime.h>
#include <cuda_fp16.h>
#include <math.h>
#include <cstdint>

// Problem constants: B=4, L=2048, D=1024, H=16, Dh=64, 3D=3072
#define BATCH   4
#define SEQ     2048
#define EMBD    1024
#define NHEAD   16
#define HDIM    64
#define TOKENS  (BATCH * SEQ)            // 8192
#define QKVDIM  (3 * EMBD)               // 3072

// ---------------- scratch (static __device__, no allocation) ----------------
__device__ __half g_q[(size_t)BATCH * NHEAD * SEQ * HDIM];  // [B,H,L,Dh] /8, perm16
__device__ __half g_k[(size_t)BATCH * NHEAD * SEQ * HDIM];  // perm16
__device__ __half g_v[(size_t)BATCH * NHEAD * HDIM * SEQ];  // [B,H,Dh,L] (transposed!)
__device__ __half g_att[(size_t)TOKENS * EMBD];             // [B,L,D] perm16
__device__ float2 g_rope[(size_t)SEQ * 32];                 // cos/sin table
__device__ __half g_xh[(size_t)TOKENS * EMBD];              // x fp16, perm16
__device__ __half g_wqkvT[(size_t)QKVDIM * EMBD];           // W_qkv^T fp16, perm16
__device__ __half g_wprojT[(size_t)EMBD * EMBD];            // W_proj^T fp16, perm16

// ---------------- helpers ---------------------------------------------------
__device__ __forceinline__ void mma_f16(float* d, const uint32_t* a,
                                        const uint32_t* b) {
  asm volatile(
      "mma.sync.aligned.m16n8k16.row.col.f32.f16.f16.f32 "
      "{%0,%1,%2,%3},{%4,%5,%6,%7},{%8,%9},{%0,%1,%2,%3};"
      : "+f"(d[0]), "+f"(d[1]), "+f"(d[2]), "+f"(d[3])
      : "r"(a[0]), "r"(a[1]), "r"(a[2]), "r"(a[3]), "r"(b[0]), "r"(b[1]));
}

#define CPA16(dst, src) \
  asm volatile("cp.async.cg.shared.global [%0], [%1], 16;\n" ::"r"(dst), "l"(src))

// 16-group permutation: pair j (0..7) goes to pair position (j&3)*2 + (j>>2).
// Thread tig then finds k={2t,2t+1,2t+8,2t+9} contiguous at offset 4t.
__device__ __host__ __forceinline__ int perm16(int k) {
  const int j = (k & 15) >> 1;
  return (k & ~15) + (((j & 3) * 2 + (j >> 2)) << 1) + (k & 1);
}

// ---------------- RoPE cos/sin table ----------------------------------------
__global__ __launch_bounds__(256) void rope_table_kernel() {
  const int idx = blockIdx.x * 256 + threadIdx.x;  // 0..65535
  const int l = idx >> 5, i = idx & 31;
  const float inv_freq = 1.0f / powf(10000.0f, (2.0f * (float)i) / 64.0f);
  float s, c;
  sincosf((float)l * inv_freq, &s, &c);
  g_rope[idx] = make_float2(c, s);
}

// ------------- fp16 round + 16-group permute (A operands) -------------------
__global__ __launch_bounds__(256) void round_permute_half(
    const float* __restrict__ in, __half* __restrict__ out, int n16) {
  int i = blockIdx.x * 256 + threadIdx.x;  // one 16-float group per thread
  const int stride = gridDim.x * 256;
  for (; i < n16; i += stride) {
    const float4* ip = (const float4*)(in + 16 * (size_t)i);
    float v[16];
    *(float4*)(v + 0) = ip[0];
    *(float4*)(v + 4) = ip[1];
    *(float4*)(v + 8) = ip[2];
    *(float4*)(v + 12) = ip[3];
    __half h[16];
#pragma unroll
    for (int j = 0; j < 8; j++) {
      const int pp = (j & 3) * 2 + (j >> 2);
      h[pp * 2] = __float2half_rn(v[2 * j]);
      h[pp * 2 + 1] = __float2half_rn(v[2 * j + 1]);
    }
    uint4* op = (uint4*)(out + 16 * (size_t)i);
    op[0] = *(uint4*)(h);
    op[1] = *(uint4*)(h + 8);
  }
}

// ------------- transpose + fp16 round + permute (B/weight operands) ---------
// in: [K][N] row-major -> out: [N][K] fp16, k 16-group permuted
__global__ __launch_bounds__(256) void transpose_permute_half(
    const float* __restrict__ in, __half* __restrict__ out, int K, int N) {
  __shared__ float tile[32][33];
  const int k0 = blockIdx.y * 32, n0 = blockIdx.x * 32;
  const int tx = threadIdx.x, ty = threadIdx.y;  // 32 x 8
#pragma unroll
  for (int i = 0; i < 32; i += 8)
    tile[ty + i][tx] = in[(size_t)(k0 + ty + i) * N + n0 + tx];
  __syncthreads();
  const int pk = perm16(tx);
#pragma unroll
  for (int i = 0; i < 32; i += 8) {
    const int n = ty + i;
    out[(size_t)(n0 + n) * K + k0 + pk] = __float2half_rn(tile[tx][n]);
  }
}

// ---------------- GEMM core (fp16 operands, fp32 accum) ---------------------
// A: [M][K] perm16; BT: [N][K] perm16. BK=32. 128x128 tile, 256 threads.
#define ABS_H 48                        // smem row stride in halves (96B)
#define AB_BUF_H (128 * ABS_H)          // 6144 halves
#define GEMM_SMEM (4 * AB_BUF_H * 2)    // 49152 B

__device__ __forceinline__ void gemm_tile_compute(
    const __half* __restrict__ A, const __half* __restrict__ BT, __half* sm,
    int m0, int n0, int K, float acc[4][4][4]) {
  const int tid = threadIdx.x;
  const int warp = tid >> 5, lane = tid & 31;
  const int wm = warp >> 2, wn = warp & 3;
  const int g = lane >> 2, tig = lane & 3;

#pragma unroll
  for (int i = 0; i < 4; i++)
#pragma unroll
    for (int j = 0; j < 4; j++)
#pragma unroll
      for (int t = 0; t < 4; t++) acc[i][j][t] = 0.0f;

  auto prefetch = [&](int kt, int buf) {
    __half* As = sm + buf * AB_BUF_H;
    __half* Bs = sm + 2 * AB_BUF_H + buf * AB_BUF_H;
    const int k0 = kt << 5;
#pragma unroll
    for (int j = 0; j < 2; j++) {
      const int p = tid + (j << 8);
      const int r = p >> 2, c = (p & 3) << 3;  // 128 rows x 4 16B-chunks
      uint32_t da = (uint32_t)__cvta_generic_to_shared(As + r * ABS_H + c);
      CPA16(da, A + (size_t)(m0 + r) * K + k0 + c);
      uint32_t db = (uint32_t)__cvta_generic_to_shared(Bs + r * ABS_H + c);
      CPA16(db, BT + (size_t)(n0 + r) * K + k0 + c);
    }
    asm volatile("cp.async.commit_group;\n");
  };

  const int NT = K >> 5;
  prefetch(0, 0);

  for (int kt = 0; kt < NT; kt++) {
    const int buf = kt & 1;
    if (kt + 1 < NT) {
      prefetch(kt + 1, buf ^ 1);
      asm volatile("cp.async.wait_group 1;\n");
    } else {
      asm volatile("cp.async.wait_group 0;\n");
    }
    __syncthreads();

    const __half* As = sm + buf * AB_BUF_H;
    const __half* Bs = sm + 2 * AB_BUF_H + buf * AB_BUF_H;

#pragma unroll
    for (int ks = 0; ks < 2; ks++) {
      const int koff = ks * 16 + 4 * tig;
      uint32_t af[4][4], bf[4][2];
#pragma unroll
      for (int mt = 0; mt < 4; mt++) {
        const int row = wm * 64 + mt * 16 + g;
        uint2 a02 = *(const uint2*)(As + row * ABS_H + koff);
        uint2 a13 = *(const uint2*)(As + (row + 8) * ABS_H + koff);
        af[mt][0] = a02.x;
        af[mt][2] = a02.y;
        af[mt][1] = a13.x;
        af[mt][3] = a13.y;
      }
#pragma unroll
      for (int nt = 0; nt < 4; nt++) {
        const int nrow = wn * 32 + nt * 8 + g;
        uint2 b01 = *(const uint2*)(Bs + nrow * ABS_H + koff);
        bf[nt][0] = b01.x;
        bf[nt][1] = b01.y;
      }
#pragma unroll
      for (int mt = 0; mt < 4; mt++)
#pragma unroll
        for (int nt = 0; nt < 4; nt++) mma_f16(acc[mt][nt], af[mt], bf[nt]);
    }
    __syncthreads();
  }
}

// ---------------- plain GEMM + bias (proj, fp32 out) ------------------------
__global__ __launch_bounds__(256) void gemm_f16_kernel(
    const __half* __restrict__ A, const __half* __restrict__ BT,
    const float* __restrict__ bias, float* __restrict__ C, int N, int K) {
  extern __shared__ __half smh[];
  const int tid = threadIdx.x;
  const int warp = tid >> 5, lane = tid & 31;
  const int wm = warp >> 2, wn = warp & 3;
  const int g = lane >> 2, tig = lane & 3;
  const int m0 = blockIdx.y << 7, n0 = blockIdx.x << 7;

  float acc[4][4][4];
  gemm_tile_compute(A, BT, smh, m0, n0, K, acc);

#pragma unroll
  for (int mt = 0; mt < 4; mt++) {
    const int r = m0 + wm * 64 + mt * 16 + g;
#pragma unroll
    for (int nt = 0; nt < 4; nt++) {
      const int c = n0 + wn * 32 + nt * 8 + 2 * tig;
      const float b0 = __ldg(bias + c), b1 = __ldg(bias + c + 1);
      float2 v0 = {acc[mt][nt][0] + b0, acc[mt][nt][1] + b1};
      float2 v1 = {acc[mt][nt][2] + b0, acc[mt][nt][3] + b1};
      *(float2*)(C + (size_t)r * N + c) = v0;
      *(float2*)(C + (size_t)(r + 8) * N + c) = v1;
    }
  }
}

// ---------------- QKV GEMM with fused RoPE/split epilogue -------------------
// Q: rotated, /8, perm16, [B,H,L,Dh]. K: rotated, perm16. V: [B,H,Dh,L].
__global__ __launch_bounds__(256) void gemm_qkv_rope_kernel(
    const __half* __restrict__ A, const __half* __restrict__ BT,
    const float* __restrict__ bias, __half* __restrict__ Q,
    __half* __restrict__ K, __half* __restrict__ V) {
  extern __shared__ __half smh[];
  const int tid = threadIdx.x;
  const int warp = tid >> 5, lane = tid & 31;
  const int wm = warp >> 2, wn = warp & 3;
  const int g = lane >> 2, tig = lane & 3;
  const int m0 = blockIdx.y << 7, n0 = blockIdx.x << 7;

  float acc[4][4][4];
  gemm_tile_compute(A, BT, smh, m0, n0, EMBD, acc);

  const int seg = n0 >> 10;  // 0=q, 1=k, 2=v (block-uniform)

#pragma unroll
  for (int mt = 0; mt < 4; mt++) {
    const int r = m0 + wm * 64 + mt * 16 + g;  // token row (and r+8)
#pragma unroll
    for (int nt = 0; nt < 4; nt++) {
      const int c = n0 + wn * 32 + nt * 8 + 2 * tig;  // even column
      const float b0 = __ldg(bias + c), b1 = __ldg(bias + c + 1);
      const int d = c & 63;            // dim within head (even)
      const int h = (c & 1023) >> 6;   // head
      const int i = d >> 1;            // rope pair index
      float vals[2][2] = {{acc[mt][nt][0] + b0, acc[mt][nt][1] + b1},
                          {acc[mt][nt][2] + b0, acc[mt][nt][3] + b1}};
#pragma unroll
      for (int rr = 0; rr < 2; rr++) {
        const int m = r + rr * 8;
        const int bb = m >> 11, l = m & 2047;
        const float x1 = vals[rr][0], x2 = vals[rr][1];
        if (seg == 2) {
          __half* vp = V + ((size_t)(bb * NHEAD + h) * HDIM + d) * SEQ + l;
          vp[0] = __float2half_rn(x1);
          vp[SEQ] = __float2half_rn(x2);
        } else {
          const float2 cs = g_rope[l * 32 + i];
          float y1 = x1 * cs.x - x2 * cs.y;
          float y2 = x1 * cs.y + x2 * cs.x;
          if (seg == 0) { y1 *= 0.125f; y2 *= 0.125f; }
          const int j = (d & 15) >> 1;
          const int pd = (d & ~15) + (((j & 3) * 2 + (j >> 2)) << 1);
          __half* dp = (seg == 0 ? Q : K) +
                       ((size_t)(bb * NHEAD + h) * SEQ + l) * HDIM + pd;
          *(__half2*)dp = __floats2half2_rn(y1, y2);
        }
      }
    }
  }
}

// ---------------- fp16 tensor-core causal flash attention -------------------
// 128 q-rows per block, 8 warps, BN=64 keys/tile, double-buffered cp.async.
#define KS_H 80    // K tile row stride (halves)
#define VT_H 72    // Vt tile row stride
#define PS_H 72    // P/Q staging stride
#define KBUF_H (64 * KS_H)
#define VBUF_H (64 * VT_H)
#define PS_BUF_H (128 * PS_H)
#define FLASH_SMEM ((2 * KBUF_H + 2 * VBUF_H + PS_BUF_H) * 2 + 2 * 64 * 4)

__global__ __launch_bounds__(256, 2) void flash_mma_kernel(
    const __half* __restrict__ Q, const __half* __restrict__ K,
    const __half* __restrict__ V, const int* __restrict__ amask,
    __half* __restrict__ O) {
  extern __shared__ __half smh[];
  __half* Ksb = smh;
  __half* Vtb = Ksb + 2 * KBUF_H;
  __half* Ps = Vtb + 2 * VBUF_H;
  int* msk = (int*)(Ps + PS_BUF_H);  // [2][64]

  const int tid = threadIdx.x;
  const int warp = tid >> 5, lane = tid & 31;
  const int g = lane >> 2, tig = lane & 3;
  const int bx = (int)(gridDim.x - 1 - blockIdx.x);  // heavy blocks first
  const int h = blockIdx.y, b = blockIdx.z;
  const int q0 = bx << 7;
  const size_t base = (size_t)(b * NHEAD + h) * SEQ * HDIM;
  const size_t vbase = (size_t)(b * NHEAD + h) * HDIM * SEQ;

  // ---- stage Q tile (128x64 halves) through Ps, hoist fragments ----
#pragma unroll
  for (int i = 0; i < 4; i++) {
    const int p = tid + (i << 8);
    const int r = p >> 3, c = (p & 7) << 3;
    *(uint4*)(Ps + r * PS_H + c) =
        *(const uint4*)(Q + base + (size_t)(q0 + r) * HDIM + c);
  }
  __syncthreads();
  uint32_t qf[4][4];
  {
    const __half* qb = Ps + (warp * 16 + g) * PS_H;
#pragma unroll
    for (int ks = 0; ks < 4; ks++) {
      const int off = ks * 16 + 4 * tig;
      uint2 q02 = *(const uint2*)(qb + off);
      uint2 q13 = *(const uint2*)(qb + 8 * PS_H + off);
      qf[ks][0] = q02.x;
      qf[ks][2] = q02.y;
      qf[ks][1] = q13.x;
      qf[ks][3] = q13.y;
    }
  }
  __syncthreads();  // Ps becomes per-warp P staging

  auto prefetch = [&](int kt, int buf) {
    const int k0 = kt << 6;
    __half* Ks_ = Ksb + buf * KBUF_H;
    __half* Vt_ = Vtb + buf * VBUF_H;
#pragma unroll
    for (int i = 0; i < 2; i++) {
      const int p = tid + (i << 8);
      const int r = p >> 3, c = (p & 7) << 3;  // 64 rows x 8 16B-chunks
      uint32_t dk = (uint32_t)__cvta_generic_to_shared(Ks_ + r * KS_H + c);
      CPA16(dk, K + base + (size_t)(k0 + r) * HDIM + c);
      uint32_t dv = (uint32_t)__cvta_generic_to_shared(Vt_ + r * VT_H + c);
      CPA16(dv, V + vbase + (size_t)r * SEQ + k0 + c);
    }
    if (tid < 64) msk[buf * 64 + tid] = amask[b * SEQ + k0 + tid];
  };

  float m0 = -1e30f, m1 = -1e30f, l0 = 0.0f, l1 = 0.0f;
  float o[8][4];
#pragma unroll
  for (int nt = 0; nt < 8; nt++)
#pragma unroll
    for (int c = 0; c < 4; c++) o[nt][c] = 0.0f;

  const int NT = (q0 >> 6) + 2;
  const int rg0 = q0 + warp * 16 + g;

  prefetch(0, 0);
  asm volatile("cp.async.commit_group;\n");

  for (int kt = 0; kt < NT; kt++) {
    const int buf = kt & 1;
    if (kt + 1 < NT) prefetch(kt + 1, buf ^ 1);
    asm volatile("cp.async.commit_group;\n");
    asm volatile("cp.async.wait_group 1;\n");
    __syncthreads();

    const __half* Ks_ = Ksb + buf * KBUF_H;
    const __half* Vt_ = Vtb + buf * VBUF_H;
    const int* mk = msk + buf * 64;

    // ---- S = (Q/8) @ K^T  (fp16 mma, K=64 over 4 steps) ----
    float s[8][4];
#pragma unroll
    for (int nt = 0; nt < 8; nt++)
#pragma unroll
      for (int c = 0; c < 4; c++) s[nt][c] = 0.0f;

#pragma unroll
    for (int ks = 0; ks < 4; ks++) {
      const int off = ks * 16 + 4 * tig;
#pragma unroll
      for (int nt = 0; nt < 8; nt++) {
        uint2 bv = *(const uint2*)(Ks_ + (nt * 8 + g) * KS_H + off);
        uint32_t bf[2] = {bv.x, bv.y};
        mma_f16(s[nt], qf[ks], bf);
      }
    }

    // ---- mask ----
    if (kt >= NT - 2) {
      const int k0 = kt << 6;
#pragma unroll
      for (int nt = 0; nt < 8; nt++) {
        const int cg = k0 + nt * 8 + 2 * tig;
        const int m_a = mk[nt * 8 + 2 * tig], m_b = mk[nt * 8 + 2 * tig + 1];
        if (!(m_a && cg <= rg0)) s[nt][0] = -1e30f;
        if (!(m_b && cg + 1 <= rg0)) s[nt][1] = -1e30f;
        if (!(m_a && cg <= rg0 + 8)) s[nt][2] = -1e30f;
        if (!(m_b && cg + 1 <= rg0 + 8)) s[nt][3] = -1e30f;
      }
    } else {
#pragma unroll
      for (int nt = 0; nt < 8; nt++) {
        const int m_a = mk[nt * 8 + 2 * tig], m_b = mk[nt * 8 + 2 * tig + 1];
        if (!m_a) { s[nt][0] = -1e30f; s[nt][2] = -1e30f; }
        if (!m_b) { s[nt][1] = -1e30f; s[nt][3] = -1e30f; }
      }
    }

    // ---- online softmax ----
    float mx0 = -1e30f, mx1 = -1e30f;
#pragma unroll
    for (int nt = 0; nt < 8; nt++) {
      mx0 = fmaxf(mx0, fmaxf(s[nt][0], s[nt][1]));
      mx1 = fmaxf(mx1, fmaxf(s[nt][2], s[nt][3]));
    }
    mx0 = fmaxf(mx0, __shfl_xor_sync(0xffffffffu, mx0, 1));
    mx0 = fmaxf(mx0, __shfl_xor_sync(0xffffffffu, mx0, 2));
    mx1 = fmaxf(mx1, __shfl_xor_sync(0xffffffffu, mx1, 1));
    mx1 = fmaxf(mx1, __shfl_xor_sync(0xffffffffu, mx1, 2));
    const float nm0 = fmaxf(m0, mx0), nm1 = fmaxf(m1, mx1);
    const float corr0 = __expf(m0 - nm0), corr1 = __expf(m1 - nm1);
    m0 = nm0;
    m1 = nm1;

    float sum0 = 0.0f, sum1 = 0.0f;
#pragma unroll
    for (int nt = 0; nt < 8; nt++) {
      s[nt][0] = __expf(s[nt][0] - nm0);
      s[nt][1] = __expf(s[nt][1] - nm0);
      s[nt][2] = __expf(s[nt][2] - nm1);
      s[nt][3] = __expf(s[nt][3] - nm1);
      sum0 += s[nt][0] + s[nt][1];
      sum1 += s[nt][2] + s[nt][3];
    }
    sum0 += __shfl_xor_sync(0xffffffffu, sum0, 1);
    sum0 += __shfl_xor_sync(0xffffffffu, sum0, 2);
    sum1 += __shfl_xor_sync(0xffffffffu, sum1, 1);
    sum1 += __shfl_xor_sync(0xffffffffu, sum1, 2);
    l0 = l0 * corr0 + sum0;
    l1 = l1 * corr1 + sum1;

#pragma unroll
    for (int nt = 0; nt < 8; nt++) {
      o[nt][0] *= corr0;
      o[nt][1] *= corr0;
      o[nt][2] *= corr1;
      o[nt][3] *= corr1;
    }

    // ---- stage P as fp16 (C-layout -> A-layout) in per-warp Ps region ----
    __half* pr = Ps + (warp * 16 + g) * PS_H;
#pragma unroll
    for (int nt = 0; nt < 8; nt++) {
      const int c0 = nt * 8 + 2 * tig;
      *(__half2*)(pr + c0) = __floats2half2_rn(s[nt][0], s[nt][1]);
      *(__half2*)(pr + 8 * PS_H + c0) = __floats2half2_rn(s[nt][2], s[nt][3]);
    }
    __syncwarp();

    // ---- O += P @ V  (fp16 mma, K=64 keys over 4 steps) ----
    const __half* pb = Ps + (warp * 16 + g) * PS_H;
#pragma unroll
    for (int ks = 0; ks < 4; ks++) {
      const int off = ks * 16 + 2 * tig;
      uint32_t a[4];
      a[0] = *(const uint32_t*)(pb + off);
      a[1] = *(const uint32_t*)(pb + 8 * PS_H + off);
      a[2] = *(const uint32_t*)(pb + off + 8);
      a[3] = *(const uint32_t*)(pb + 8 * PS_H + off + 8);
#pragma unroll
      for (int nt = 0; nt < 8; nt++) {
        const __half* vb = Vt_ + (nt * 8 + g) * VT_H + off;
        uint32_t bf[2];
        bf[0] = *(const uint32_t*)(vb);
        bf[1] = *(const uint32_t*)(vb + 8);
        mma_f16(o[nt], a, bf);
      }
    }
    __syncthreads();  // all warps done with tiles[buf] before refill
  }

  // ---- write O fp16 perm16 to [B, L, H*Dh] for the proj GEMM ----
  const float inv0 = 1.0f / l0, inv1 = 1.0f / l1;
#pragma unroll
  for (int nt = 0; nt < 8; nt++) {
    const int dl = nt * 8 + 2 * tig;
    const int j = (dl & 15) >> 1;
    const int col = h * HDIM + (dl & ~15) + (((j & 3) * 2 + (j >> 2)) << 1);
    *(__half2*)(O + (size_t)(b * SEQ + rg0) * EMBD + col) =
        __floats2half2_rn(o[nt][0] * inv0, o[nt][1] * inv0);
    *(__half2*)(O + (size_t)(b * SEQ + rg0 + 8) * EMBD + col) =
        __floats2half2_rn(o[nt][2] * inv1, o[nt][3] * inv1);
  }
}

// ---------------------------------------------------------------------------
extern "C" void kernel_launch(void* const* d_in, const int* in_sizes, int n_in,
                              void* d_out, int out_size) {
  const float* x     = (const float*)d_in[0];
  const float* Wqkv  = (const float*)d_in[1];
  const float* bqkv  = (const float*)d_in[2];
  const float* Wproj = (const float*)d_in[3];
  const float* bproj = (const float*)d_in[4];
  const int*   amask = (const int*)d_in[5];
  float* out = (float*)d_out;

  __half *q, *k, *v, *att, *xh, *wqkvT, *wprojT;
  cudaGetSymbolAddress((void**)&q, g_q);
  cudaGetSymbolAddress((void**)&k, g_k);
  cudaGetSymbolAddress((void**)&v, g_v);
  cudaGetSymbolAddress((void**)&att, g_att);
  cudaGetSymbolAddress((void**)&xh, g_xh);
  cudaGetSymbolAddress((void**)&wqkvT, g_wqkvT);
  cudaGetSymbolAddress((void**)&wprojT, g_wprojT);

  cudaFuncSetAttribute(gemm_f16_kernel,
                       cudaFuncAttributeMaxDynamicSharedMemorySize, GEMM_SMEM);
  cudaFuncSetAttribute(gemm_qkv_rope_kernel,
                       cudaFuncAttributeMaxDynamicSharedMemorySize, GEMM_SMEM);
  cudaFuncSetAttribute(flash_mma_kernel,
                       cudaFuncAttributeMaxDynamicSharedMemorySize, FLASH_SMEM);

  // 0. RoPE table + operand preparation (fp16 round / permute / transpose)
  rope_table_kernel<<<SEQ * 32 / 256, 256>>>();
  round_permute_half<<<1184, 256>>>(x, xh, TOKENS * EMBD / 16);
  {
    dim3 gt1(QKVDIM / 32, EMBD / 32);
    transpose_permute_half<<<gt1, dim3(32, 8)>>>(Wqkv, wqkvT, EMBD, QKVDIM);
    dim3 gt2(EMBD / 32, EMBD / 32);
    transpose_permute_half<<<gt2, dim3(32, 8)>>>(Wproj, wprojT, EMBD, EMBD);
  }

  // 1. QKV projection + fused RoPE/split -> q (/8), k, v
  dim3 g1(QKVDIM / 128, TOKENS / 128);
  gemm_qkv_rope_kernel<<<g1, 256, GEMM_SMEM>>>(xh, wqkvT, bqkv, q, k, v);

  // 2. Causal flash attention (fp16 tensor cores) -> att (fp16, perm16)
  dim3 g3(SEQ / 128, NHEAD, BATCH);
  flash_mma_kernel<<<g3, 256, FLASH_SMEM>>>(q, k, v, amask, att);

  // 3. Output projection -> fp32 out
  dim3 g4(EMBD / 128, TOKENS / 128);
  gemm_f16_kernel<<<g4, 256, GEMM_SMEM>>>(att, wprojT, bproj, out, EMBD, EMBD);
}